// round 5
// baseline (speedup 1.0000x reference)
#include <cuda_runtime.h>
#include <cuda_bf16.h>
#include <cstdint>

#define NN 100000
#define NE 1600000
#define FH 128
#define CC 64

// ---------------- scratch ----------------
__device__ float g_h[3ll * NN * FH];   // h1,h2,h3
__device__ float g_y[(long long)NN * FH];
__device__ float g_z[(long long)NN * CC];
__device__ float g_onorm[NN];
__device__ float g_inorm[NN];
__device__ int   g_indeg[NN];
__device__ int   g_outdeg[NN];
__device__ int   g_rs[NN + 1];
__device__ int   g_cur[NN];
__device__ int   g_perm[NE];

// ---------------- helpers ----------------
__device__ __forceinline__ uint32_t to_tf32(float x) {
    uint32_t y;
    asm("cvt.rna.tf32.f32 %0, %1;" : "=r"(y) : "f"(x));
    return y;
}
__device__ __forceinline__ float to_tf32f(float x) {
    return __uint_as_float(to_tf32(x));
}

__device__ __forceinline__ void mma_tf32(float* c, const uint32_t* a, uint32_t b0, uint32_t b1) {
    asm volatile(
        "mma.sync.aligned.m16n8k8.row.col.f32.tf32.tf32.f32 "
        "{%0,%1,%2,%3}, {%4,%5,%6,%7}, {%8,%9}, {%0,%1,%2,%3};"
        : "+f"(c[0]), "+f"(c[1]), "+f"(c[2]), "+f"(c[3])
        : "r"(a[0]), "r"(a[1]), "r"(a[2]), "r"(a[3]), "r"(b0), "r"(b1));
}

// ---------------- graph prep ----------------
__global__ void k_zero() {
    int i = blockIdx.x * blockDim.x + threadIdx.x;
    if (i < NN) { g_indeg[i] = 0; g_outdeg[i] = 0; }
}

__global__ void k_degree(const int* __restrict__ src, const int* __restrict__ dst) {
    int e = blockIdx.x * blockDim.x + threadIdx.x;
    if (e < NE) {
        atomicAdd(&g_outdeg[src[e]], 1);
        atomicAdd(&g_indeg[dst[e]], 1);
    }
}

// exclusive scan of indeg -> rs/cur, plus norms (fused)
__global__ __launch_bounds__(1024) void k_scan() {
    __shared__ int sums[1024];
    int tid = threadIdx.x;
    const int chunk = (NN + 1023) / 1024;
    int b = tid * chunk;
    int e = min(b + chunk, NN);
    int s = 0;
    for (int i = b; i < e; i++) {
        int id = g_indeg[i];
        int od = g_outdeg[i];
        s += id;
        g_inorm[i] = id > 0 ? rsqrtf((float)id) : 0.f;
        g_onorm[i] = od > 0 ? rsqrtf((float)od) : 0.f;
    }
    sums[tid] = s;
    __syncthreads();
    for (int off = 1; off < 1024; off <<= 1) {
        int v = (tid >= off) ? sums[tid - off] : 0;
        __syncthreads();
        sums[tid] += v;
        __syncthreads();
    }
    int run = (tid == 0) ? 0 : sums[tid - 1];
    for (int i = b; i < e; i++) {
        g_rs[i] = run;
        g_cur[i] = run;
        run += g_indeg[i];
    }
    if (tid == 1023) g_rs[NN] = run;
}

__global__ void k_build(const int* __restrict__ src, const int* __restrict__ dst) {
    int e = blockIdx.x * blockDim.x + threadIdx.x;
    if (e < NE) {
        int p = atomicAdd(&g_cur[dst[e]], 1);
        g_perm[p] = src[e];
    }
}

// ---------------- TF32 GEMM: Y[N,128] = (X .* onorm) @ W[128,128] ----------------
// 256 thr (8 warps), tile M=128, N=128. Register-prefetch software pipeline over 4 k-chunks.
__global__ __launch_bounds__(256) void k_gemm_conv_tc(const float* __restrict__ X,
                                                      const float* __restrict__ W,
                                                      float* __restrict__ Y) {
    __shared__ float As[128][36];   // [m][k] pad->stride%32=4
    __shared__ float Ws[32][136];   // [k][n] pad->stride%32=8
    int tid = threadIdx.x;
    int warp = tid >> 5, lane = tid & 31;
    int gid = lane >> 2, tig = lane & 3;
    int row0 = blockIdx.x * 128;

    float acc[16][4];
#pragma unroll
    for (int i = 0; i < 16; i++)
#pragma unroll
        for (int j = 0; j < 4; j++) acc[i][j] = 0.f;

    float4 pa[4], pw[4];
    float on[4];

    auto ldA = [&](int k0) {
#pragma unroll
        for (int u = 0; u < 4; u++) {
            int i = tid + u * 256;
            int m = i >> 3, kq = (i & 7) * 4;
            int r = row0 + m;
            if (r < NN) { pa[u] = *(const float4*)&X[r * 128 + k0 + kq]; on[u] = g_onorm[r]; }
            else        { pa[u] = make_float4(0.f, 0.f, 0.f, 0.f); on[u] = 0.f; }
        }
    };
    auto ldW = [&](int k0) {
#pragma unroll
        for (int u = 0; u < 4; u++) {
            int i = tid + u * 256;
            int k = i >> 5, nq = (i & 31) * 4;
            pw[u] = *(const float4*)&W[(k0 + k) * 128 + nq];
        }
    };
    auto stAW = [&]() {
#pragma unroll
        for (int u = 0; u < 4; u++) {
            int i = tid + u * 256;
            int m = i >> 3, kq = (i & 7) * 4;
            As[m][kq + 0] = to_tf32f(pa[u].x * on[u]);
            As[m][kq + 1] = to_tf32f(pa[u].y * on[u]);
            As[m][kq + 2] = to_tf32f(pa[u].z * on[u]);
            As[m][kq + 3] = to_tf32f(pa[u].w * on[u]);
            int k = i >> 5, nq = (i & 31) * 4;
            Ws[k][nq + 0] = to_tf32f(pw[u].x);
            Ws[k][nq + 1] = to_tf32f(pw[u].y);
            Ws[k][nq + 2] = to_tf32f(pw[u].z);
            Ws[k][nq + 3] = to_tf32f(pw[u].w);
        }
    };

    ldA(0); ldW(0);
    stAW();
    __syncthreads();

    for (int kc = 0; kc < 4; kc++) {
        if (kc < 3) { ldA((kc + 1) * 32); ldW((kc + 1) * 32); }  // prefetch overlapped with mma
#pragma unroll
        for (int ks = 0; ks < 4; ks++) {
            int kk = ks * 8;
            uint32_t a[4];
            a[0] = __float_as_uint(As[warp * 16 + gid][kk + tig]);
            a[1] = __float_as_uint(As[warp * 16 + gid + 8][kk + tig]);
            a[2] = __float_as_uint(As[warp * 16 + gid][kk + tig + 4]);
            a[3] = __float_as_uint(As[warp * 16 + gid + 8][kk + tig + 4]);
#pragma unroll
            for (int nt = 0; nt < 16; nt++) {
                uint32_t b0 = __float_as_uint(Ws[kk + tig][nt * 8 + gid]);
                uint32_t b1 = __float_as_uint(Ws[kk + tig + 4][nt * 8 + gid]);
                mma_tf32(acc[nt], a, b0, b1);
            }
        }
        __syncthreads();
        if (kc < 3) {
            stAW();
            __syncthreads();
        }
    }

    int r0 = row0 + warp * 16 + gid;
    int r1 = r0 + 8;
#pragma unroll
    for (int nt = 0; nt < 16; nt++) {
        int c = nt * 8 + tig * 2;
        if (r0 < NN) *(float2*)&Y[r0 * 128 + c] = make_float2(acc[nt][0], acc[nt][1]);
        if (r1 < NN) *(float2*)&Y[r1 * 128 + c] = make_float2(acc[nt][2], acc[nt][3]);
    }
}

// ---------------- TF32 GEMM: Z[N,64] = concat(h1,h2,h3) @ Wo[384,64] ----------------
__global__ __launch_bounds__(256) void k_gemm_z_tc(const float* __restrict__ Hc,
                                                   const float* __restrict__ Wo,
                                                   float* __restrict__ Z) {
    __shared__ float As[128][36];
    __shared__ float Ws[32][72];
    int tid = threadIdx.x;
    int warp = tid >> 5, lane = tid & 31;
    int gid = lane >> 2, tig = lane & 3;
    int row0 = blockIdx.x * 128;

    float acc[8][4];
#pragma unroll
    for (int i = 0; i < 8; i++)
#pragma unroll
        for (int j = 0; j < 4; j++) acc[i][j] = 0.f;

    float4 pa[4], pw[2];

    auto ldA = [&](int kc) {
        int k0 = kc * 32;
        const float* Xb = Hc + (long long)(k0 >> 7) * NN * 128;
        int cb = k0 & 127;
#pragma unroll
        for (int u = 0; u < 4; u++) {
            int i = tid + u * 256;
            int m = i >> 3, kq = (i & 7) * 4;
            int r = row0 + m;
            pa[u] = (r < NN) ? *(const float4*)&Xb[r * 128 + cb + kq]
                             : make_float4(0.f, 0.f, 0.f, 0.f);
        }
    };
    auto ldW = [&](int kc) {
        int k0 = kc * 32;
#pragma unroll
        for (int u = 0; u < 2; u++) {
            int i = tid + u * 256;
            int k = i >> 4, nq = (i & 15) * 4;
            pw[u] = *(const float4*)&Wo[(k0 + k) * 64 + nq];
        }
    };
    auto stAW = [&]() {
#pragma unroll
        for (int u = 0; u < 4; u++) {
            int i = tid + u * 256;
            int m = i >> 3, kq = (i & 7) * 4;
            As[m][kq + 0] = to_tf32f(pa[u].x);
            As[m][kq + 1] = to_tf32f(pa[u].y);
            As[m][kq + 2] = to_tf32f(pa[u].z);
            As[m][kq + 3] = to_tf32f(pa[u].w);
        }
#pragma unroll
        for (int u = 0; u < 2; u++) {
            int i = tid + u * 256;
            int k = i >> 4, nq = (i & 15) * 4;
            Ws[k][nq + 0] = to_tf32f(pw[u].x);
            Ws[k][nq + 1] = to_tf32f(pw[u].y);
            Ws[k][nq + 2] = to_tf32f(pw[u].z);
            Ws[k][nq + 3] = to_tf32f(pw[u].w);
        }
    };

    ldA(0); ldW(0);
    stAW();
    __syncthreads();

    for (int kc = 0; kc < 12; kc++) {
        if (kc < 11) { ldA(kc + 1); ldW(kc + 1); }
#pragma unroll
        for (int ks = 0; ks < 4; ks++) {
            int kk = ks * 8;
            uint32_t a[4];
            a[0] = __float_as_uint(As[warp * 16 + gid][kk + tig]);
            a[1] = __float_as_uint(As[warp * 16 + gid + 8][kk + tig]);
            a[2] = __float_as_uint(As[warp * 16 + gid][kk + tig + 4]);
            a[3] = __float_as_uint(As[warp * 16 + gid + 8][kk + tig + 4]);
#pragma unroll
            for (int nt = 0; nt < 8; nt++) {
                uint32_t b0 = __float_as_uint(Ws[kk + tig][nt * 8 + gid]);
                uint32_t b1 = __float_as_uint(Ws[kk + tig + 4][nt * 8 + gid]);
                mma_tf32(acc[nt], a, b0, b1);
            }
        }
        __syncthreads();
        if (kc < 11) {
            stAW();
            __syncthreads();
        }
    }

    int r0 = row0 + warp * 16 + gid;
    int r1 = r0 + 8;
#pragma unroll
    for (int nt = 0; nt < 8; nt++) {
        int c = nt * 8 + tig * 2;
        if (r0 < NN) *(float2*)&Z[r0 * 64 + c] = make_float2(acc[nt][0], acc[nt][1]);
        if (r1 < NN) *(float2*)&Z[r1 * 64 + c] = make_float2(acc[nt][2], acc[nt][3]);
    }
}

// ---------------- aggregation: warp per node, float4 lanes ----------------
__global__ __launch_bounds__(256) void k_agg(const float* __restrict__ Y,
                                             const float* __restrict__ b,
                                             float* __restrict__ Hout) {
    int v = (blockIdx.x * 256 + threadIdx.x) >> 5;
    if (v >= NN) return;
    int lane = threadIdx.x & 31;
    int col = lane * 4;
    int s = g_rs[v], e = g_rs[v + 1];
    float4 a0 = make_float4(0.f, 0.f, 0.f, 0.f), a1 = a0, a2 = a0, a3 = a0;
    int j = s;
    for (; j + 4 <= e; j += 4) {
        int s0 = __ldg(&g_perm[j]), s1 = __ldg(&g_perm[j + 1]);
        int s2 = __ldg(&g_perm[j + 2]), s3 = __ldg(&g_perm[j + 3]);
        float4 v0 = __ldg((const float4*)&Y[s0 * 128 + col]);
        float4 v1 = __ldg((const float4*)&Y[s1 * 128 + col]);
        float4 v2 = __ldg((const float4*)&Y[s2 * 128 + col]);
        float4 v3 = __ldg((const float4*)&Y[s3 * 128 + col]);
        a0.x += v0.x; a0.y += v0.y; a0.z += v0.z; a0.w += v0.w;
        a1.x += v1.x; a1.y += v1.y; a1.z += v1.z; a1.w += v1.w;
        a2.x += v2.x; a2.y += v2.y; a2.z += v2.z; a2.w += v2.w;
        a3.x += v3.x; a3.y += v3.y; a3.z += v3.z; a3.w += v3.w;
    }
    for (; j < e; j++) {
        float4 v0 = __ldg((const float4*)&Y[__ldg(&g_perm[j]) * 128 + col]);
        a0.x += v0.x; a0.y += v0.y; a0.z += v0.z; a0.w += v0.w;
    }
    float in = g_inorm[v];
    float4 bb = __ldg((const float4*)&b[col]);
    float4 r;
    r.x = fmaxf((a0.x + a1.x + a2.x + a3.x) * in + bb.x, 0.f);
    r.y = fmaxf((a0.y + a1.y + a2.y + a3.y) * in + bb.y, 0.f);
    r.z = fmaxf((a0.z + a1.z + a2.z + a3.z) * in + bb.z, 0.f);
    r.w = fmaxf((a0.w + a1.w + a2.w + a3.w) * in + bb.w, 0.f);
    *(float4*)&Hout[v * 128 + col] = r;
}

// ---------------- final: warp per node, float2 lanes ----------------
__global__ __launch_bounds__(256) void k_final(const float* __restrict__ bo,
                                               float* __restrict__ Out) {
    int v = (blockIdx.x * 256 + threadIdx.x) >> 5;
    if (v >= NN) return;
    int lane = threadIdx.x & 31;
    int col = lane * 2;
    int s = g_rs[v], e = g_rs[v + 1];
    float2 a0 = make_float2(0.f, 0.f), a1 = a0, a2 = a0, a3 = a0;
    int j = s;
    for (; j + 4 <= e; j += 4) {
        int s0 = __ldg(&g_perm[j]), s1 = __ldg(&g_perm[j + 1]);
        int s2 = __ldg(&g_perm[j + 2]), s3 = __ldg(&g_perm[j + 3]);
        float2 v0 = __ldg((const float2*)&g_z[s0 * 64 + col]);
        float2 v1 = __ldg((const float2*)&g_z[s1 * 64 + col]);
        float2 v2 = __ldg((const float2*)&g_z[s2 * 64 + col]);
        float2 v3 = __ldg((const float2*)&g_z[s3 * 64 + col]);
        a0.x += v0.x; a0.y += v0.y;
        a1.x += v1.x; a1.y += v1.y;
        a2.x += v2.x; a2.y += v2.y;
        a3.x += v3.x; a3.y += v3.y;
    }
    for (; j < e; j++) {
        float2 v0 = __ldg((const float2*)&g_z[__ldg(&g_perm[j]) * 64 + col]);
        a0.x += v0.x; a0.y += v0.y;
    }
    float2 bb = __ldg((const float2*)&bo[col]);
    Out[v * 64 + col + 0] = (a0.x + a1.x) + (a2.x + a3.x) + bb.x;
    Out[v * 64 + col + 1] = (a0.y + a1.y) + (a2.y + a3.y) + bb.y;
}

// ---------------- host ----------------
extern "C" void kernel_launch(void* const* d_in, const int* in_sizes, int n_in,
                              void* d_out, int out_size) {
    const float* feats = (const float*)d_in[0];
    const int*   src   = (const int*)d_in[1];
    const int*   dst   = (const int*)d_in[2];
    const float* W0    = (const float*)d_in[3];
    const float* b0    = (const float*)d_in[4];
    const float* W1    = (const float*)d_in[5];
    const float* b1    = (const float*)d_in[6];
    const float* W2    = (const float*)d_in[7];
    const float* b2    = (const float*)d_in[8];
    const float* Wo    = (const float*)d_in[9];
    const float* bo    = (const float*)d_in[10];
    float* out = (float*)d_out;

    void *p_h, *p_y, *p_z;
    cudaGetSymbolAddress(&p_h, g_h);
    cudaGetSymbolAddress(&p_y, g_y);
    cudaGetSymbolAddress(&p_z, g_z);
    float* hbuf = (float*)p_h;
    float* ybuf = (float*)p_y;
    float* zbuf = (float*)p_z;

    int eb = (NE + 255) / 256;
    // launches ordered so ncu's fixed skip-5 window profiles k_agg (launch #6)
    k_zero<<<(NN + 255) / 256, 256>>>();          // 1
    k_degree<<<eb, 256>>>(src, dst);              // 2
    k_scan<<<1, 1024>>>();                        // 3 (norms fused)
    k_build<<<eb, 256>>>(src, dst);               // 4

    int gb = (NN + 127) / 128;
    int ab = (NN * 32 + 255) / 256;

    k_gemm_conv_tc<<<gb, 256>>>(feats, W0, ybuf);                 // 5
    k_agg<<<ab, 256>>>(ybuf, b0, hbuf);                           // 6  <- profiled
    k_gemm_conv_tc<<<gb, 256>>>(hbuf, W1, ybuf);
    k_agg<<<ab, 256>>>(ybuf, b1, hbuf + (long long)NN * 128);
    k_gemm_conv_tc<<<gb, 256>>>(hbuf + (long long)NN * 128, W2, ybuf);
    k_agg<<<ab, 256>>>(ybuf, b2, hbuf + 2ll * NN * 128);
    k_gemm_z_tc<<<gb, 256>>>(hbuf, Wo, zbuf);
    k_final<<<ab, 256>>>(bo, out);
}